// round 1
// baseline (speedup 1.0000x reference)
#include <cuda_runtime.h>
#include <math.h>

#define Bc 4
#define Nc 5
#define Cc 64
#define Hc 96
#define Wc 288
#define HWc (Hc * Wc)

// DECAY_WEIGHTS = softmax([1.0, 0.5])
#define W0c 0.6224593312018546f
#define W1c 0.3775406687981454f

__device__ float g_theta[Bc * Nc * 6];
__device__ float g_mask[Bc * HWc];
__device__ float g_dmask[Bc * HWc];

// ---------------------------------------------------------------------------
// Kernel T: build 2x3 affine thetas from pairwise_t_matrix[b, 0, n]
// ---------------------------------------------------------------------------
__global__ void theta_kernel(const float* __restrict__ pt) {
    int t = threadIdx.x;
    if (t >= Bc * Nc) return;
    int b = t / Nc, n = t % Nc;
    const float* P = pt + ((size_t)(b * Nc + 0) * Nc + n) * 16;  // 4x4 row-major
    float* th = g_theta + t * 6;
    th[0] = P[0];                                        // [0][0]
    th[1] = P[1] * ((float)Hc / (float)Wc);              // [0][1] * H/W
    th[2] = P[3] / (4.0f * 0.4f * (float)Wc) * 2.0f;     // [0][3] scaled
    th[3] = P[4] * ((float)Wc / (float)Hc);              // [1][0] * W/H
    th[4] = P[5];                                        // [1][1]
    th[5] = P[7] / (4.0f * 0.4f * (float)Hc) * 2.0f;     // [1][3] scaled
}

// ---------------------------------------------------------------------------
// Kernel A: per-pixel confidence score from x0 and x1 -> binary mask
// sc = sigmoid( sum_k softmax_k(ego.neigh_k/8) * (neigh_k . mlp_w) + b )
// ---------------------------------------------------------------------------
__global__ __launch_bounds__(128)
void score_kernel(const float* __restrict__ x0, const float* __restrict__ x1,
                  const float* __restrict__ mlp_w, const float* __restrict__ mlp_b) {
    __shared__ float sw[Cc];
    int tid = threadIdx.x;
    if (tid < Cc) sw[tid] = mlp_w[tid];
    __syncthreads();

    int p = blockIdx.x * blockDim.x + tid;
    int b = blockIdx.y;
    if (p >= HWc) return;

    float bb = __ldg(mlp_b);
    float sc[2];

    #pragma unroll
    for (int f = 0; f < 2; f++) {
        const float* xf = (f == 0) ? x0 : x1;
        const float* base = xf + (size_t)b * Nc * Cc * HWc + p;

        float ego[Cc];
        #pragma unroll
        for (int c = 0; c < Cc; c++) ego[c] = base[(size_t)c * HWc];

        float s[4], m[4];
        #pragma unroll
        for (int k = 0; k < 4; k++) {
            const float* nb = base + (size_t)(k + 1) * Cc * HWc;
            float ss = 0.f, mm = 0.f;
            #pragma unroll
            for (int c = 0; c < Cc; c++) {
                float v = nb[(size_t)c * HWc];
                ss = fmaf(ego[c], v, ss);
                mm = fmaf(sw[c], v, mm);
            }
            s[k] = ss * 0.125f;  // / sqrt(64)
            m[k] = mm;
        }

        float mx = fmaxf(fmaxf(s[0], s[1]), fmaxf(s[2], s[3]));
        float sum = 0.f, acc = 0.f;
        #pragma unroll
        for (int k = 0; k < 4; k++) {
            float e = expf(s[k] - mx);
            sum += e;
            acc = fmaf(e, m[k], acc);
        }
        float z = acc / sum + bb;
        sc[f] = 1.f / (1.f + expf(-z));
    }

    float conf = W0c * sc[0] + W1c * sc[1];
    g_mask[b * HWc + p] = (conf > 0.5f) ? 1.0f : 0.0f;
}

// ---------------------------------------------------------------------------
// Kernel B: 3x3 max dilation (SAME) of the mask
// ---------------------------------------------------------------------------
__global__ void dilate_kernel() {
    int p = blockIdx.x * blockDim.x + threadIdx.x;
    int b = blockIdx.y;
    if (p >= HWc) return;
    int i = p / Wc, j = p % Wc;
    float m = 0.f;
    #pragma unroll
    for (int di = -1; di <= 1; di++) {
        int ii = i + di;
        if (ii < 0 || ii >= Hc) continue;
        #pragma unroll
        for (int dj = -1; dj <= 1; dj++) {
            int jj = j + dj;
            if (jj < 0 || jj >= Wc) continue;
            m = fmaxf(m, g_mask[b * HWc + ii * Wc + jj]);
        }
    }
    g_dmask[b * HWc + p] = m;
}

// ---------------------------------------------------------------------------
// Kernel C: warp (bilinear, zero-pad, masked) + 5-way attention fusion
// ---------------------------------------------------------------------------
struct Taps {
    int idx[4];
    float w[4];
};

__device__ __forceinline__ Taps make_taps(int b, int n, float gx, float gy, bool use_mask) {
    const float* th = g_theta + (b * Nc + n) * 6;
    float g0 = fmaf(th[0], gx, fmaf(th[1], gy, th[2]));
    float g1 = fmaf(th[3], gx, fmaf(th[4], gy, th[5]));
    float px = (g0 + 1.f) * 0.5f * (float)(Wc - 1);
    float py = (g1 + 1.f) * 0.5f * (float)(Hc - 1);
    float x0f = floorf(px), y0f = floorf(py);
    float wx = px - x0f, wy = py - y0f;
    int xi = (int)x0f, yi = (int)y0f;

    float bw[4] = { (1.f - wx) * (1.f - wy), wx * (1.f - wy),
                    (1.f - wx) * wy,         wx * wy };
    const int dx[4] = {0, 1, 0, 1};
    const int dy[4] = {0, 0, 1, 1};

    Taps t;
    #pragma unroll
    for (int tt = 0; tt < 4; tt++) {
        int xx = xi + dx[tt], yy = yi + dy[tt];
        bool valid = (xx >= 0) & (xx <= Wc - 1) & (yy >= 0) & (yy <= Hc - 1);
        int xc = min(max(xx, 0), Wc - 1);
        int yc = min(max(yy, 0), Hc - 1);
        int idx = yc * Wc + xc;
        float mv = use_mask ? g_dmask[b * HWc + idx] : 1.f;
        t.idx[tt] = idx;
        t.w[tt] = valid ? bw[tt] * mv : 0.f;
    }
    return t;
}

__device__ __forceinline__ float sample4(const float* __restrict__ img, const Taps& t) {
    return fmaf(t.w[0], img[t.idx[0]],
           fmaf(t.w[1], img[t.idx[1]],
           fmaf(t.w[2], img[t.idx[2]],
                t.w[3] * img[t.idx[3]])));
}

__global__ __launch_bounds__(128)
void fuse_kernel(const float* __restrict__ x0, float* __restrict__ out) {
    int p = blockIdx.x * blockDim.x + threadIdx.x;
    int b = blockIdx.y;
    if (p >= HWc) return;
    int i = p / Wc, j = p % Wc;
    float gx = -1.f + 2.f * (float)j / (float)(Wc - 1);
    float gy = -1.f + 2.f * (float)i / (float)(Hc - 1);

    const float* xb = x0 + (size_t)b * Nc * Cc * HWc;

    // ego (n=0), mask == 1
    Taps t0 = make_taps(b, 0, gx, gy, false);
    float nf0[Cc];
    float s0 = 0.f;
    #pragma unroll
    for (int c = 0; c < Cc; c++) {
        const float* img = xb + (size_t)c * HWc;
        float v = sample4(img, t0);
        nf0[c] = v;
        s0 = fmaf(v, v, s0);
    }

    float s[5];
    s[0] = s0 * 0.125f;

    // pass 1: scores vs each warped neighbor
    for (int k = 1; k < Nc; k++) {
        Taps tk = make_taps(b, k, gx, gy, true);
        const float* imgb = xb + (size_t)k * Cc * HWc;
        float sk = 0.f;
        #pragma unroll
        for (int c = 0; c < Cc; c++) {
            float v = sample4(imgb + (size_t)c * HWc, tk);
            sk = fmaf(nf0[c], v, sk);
        }
        s[k] = sk * 0.125f;
    }

    // softmax over 5
    float mx = s[0];
    #pragma unroll
    for (int k = 1; k < 5; k++) mx = fmaxf(mx, s[k]);
    float a[5], sum = 0.f;
    #pragma unroll
    for (int k = 0; k < 5; k++) { a[k] = expf(s[k] - mx); sum += a[k]; }
    float inv = 1.f / sum;
    #pragma unroll
    for (int k = 0; k < 5; k++) a[k] *= inv;

    // pass 2: ctx accumulated in-place into nf0 (neighbor loads are L1-hot)
    #pragma unroll
    for (int c = 0; c < Cc; c++) nf0[c] *= a[0];

    for (int k = 1; k < Nc; k++) {
        Taps tk = make_taps(b, k, gx, gy, true);
        const float* imgb = xb + (size_t)k * Cc * HWc;
        float ak = a[k];
        #pragma unroll
        for (int c = 0; c < Cc; c++) {
            float v = sample4(imgb + (size_t)c * HWc, tk);
            nf0[c] = fmaf(ak, v, nf0[c]);
        }
    }

    #pragma unroll
    for (int c = 0; c < Cc; c++) {
        out[((size_t)b * Cc + c) * HWc + p] = nf0[c];
    }
}

// ---------------------------------------------------------------------------
// Launch
// ---------------------------------------------------------------------------
extern "C" void kernel_launch(void* const* d_in, const int* in_sizes, int n_in,
                              void* d_out, int out_size) {
    const float* x0    = (const float*)d_in[0];
    const float* x1    = (const float*)d_in[1];
    const float* pt    = (const float*)d_in[2];
    const float* mlp_w = (const float*)d_in[3];
    const float* mlp_b = (const float*)d_in[4];
    float* out = (float*)d_out;

    theta_kernel<<<1, 32>>>(pt);

    dim3 gridA((HWc + 127) / 128, Bc);
    score_kernel<<<gridA, 128>>>(x0, x1, mlp_w, mlp_b);

    dim3 gridB((HWc + 255) / 256, Bc);
    dilate_kernel<<<gridB, 256>>>();

    fuse_kernel<<<gridA, 128>>>(x0, out);
}

// round 2
// speedup vs baseline: 1.9758x; 1.9758x over previous
#include <cuda_runtime.h>
#include <math.h>

#define Bc 4
#define Nc 5
#define Cc 64
#define Hc 96
#define Wc 288
#define HWc (Hc * Wc)

// DECAY_WEIGHTS = softmax([1.0, 0.5])
#define W0c 0.6224593312018546f
#define W1c 0.3775406687981454f

#define PX 32     // pixels per block
#define CG 16     // channel groups per block
#define CPT 4     // channels per thread  (CG*CPT == Cc)

__device__ float g_theta[Bc * Nc * 6];
__device__ float g_mask[Bc * HWc];
__device__ float g_dmask[Bc * HWc];

// ---------------------------------------------------------------------------
// Kernel T: build 2x3 affine thetas from pairwise_t_matrix[b, 0, n]
// ---------------------------------------------------------------------------
__global__ void theta_kernel(const float* __restrict__ pt) {
    int t = threadIdx.x;
    if (t >= Bc * Nc) return;
    int b = t / Nc, n = t % Nc;
    const float* P = pt + ((size_t)(b * Nc + 0) * Nc + n) * 16;  // 4x4 row-major
    float* th = g_theta + t * 6;
    th[0] = P[0];
    th[1] = P[1] * ((float)Hc / (float)Wc);
    th[2] = P[3] / (4.0f * 0.4f * (float)Wc) * 2.0f;
    th[3] = P[4] * ((float)Wc / (float)Hc);
    th[4] = P[5];
    th[5] = P[7] / (4.0f * 0.4f * (float)Hc) * 2.0f;
}

// ---------------------------------------------------------------------------
// Kernel A: per-pixel confidence -> binary mask.
// Channel-split: 16 warps-worth of channel groups, smem reduction.
// ---------------------------------------------------------------------------
__global__ __launch_bounds__(PX * CG)
void score_kernel(const float* __restrict__ x0, const float* __restrict__ x1,
                  const float* __restrict__ mlp_w, const float* __restrict__ mlp_b) {
    __shared__ float sm_ss[4][CG][PX];
    __shared__ float sm_mm[4][CG][PX];

    int tx = threadIdx.x;           // pixel within block
    int ty = threadIdx.y;           // channel group
    int p  = blockIdx.x * PX + tx;
    int b  = blockIdx.y;
    int c0 = ty * CPT;

    float w[CPT];
    #pragma unroll
    for (int cc = 0; cc < CPT; cc++) w[cc] = __ldg(mlp_w + c0 + cc);
    float bb = __ldg(mlp_b);

    float conf = 0.f;
    const float dw[2] = {W0c, W1c};

    for (int f = 0; f < 2; f++) {
        const float* xf = (f == 0) ? x0 : x1;
        const float* base = xf + (size_t)b * Nc * Cc * HWc + (size_t)c0 * HWc + p;

        float e[CPT];
        #pragma unroll
        for (int cc = 0; cc < CPT; cc++) e[cc] = base[(size_t)cc * HWc];

        #pragma unroll
        for (int k = 0; k < 4; k++) {
            const float* nb = base + (size_t)(k + 1) * Cc * HWc;
            float ss = 0.f, mm = 0.f;
            #pragma unroll
            for (int cc = 0; cc < CPT; cc++) {
                float v = nb[(size_t)cc * HWc];
                ss = fmaf(e[cc], v, ss);
                mm = fmaf(w[cc], v, mm);
            }
            sm_ss[k][ty][tx] = ss;
            sm_mm[k][ty][tx] = mm;
        }
        __syncthreads();

        if (ty == 0) {
            float s[4], m[4];
            #pragma unroll
            for (int k = 0; k < 4; k++) {
                float ss = 0.f, mm = 0.f;
                #pragma unroll
                for (int cg = 0; cg < CG; cg++) {
                    ss += sm_ss[k][cg][tx];
                    mm += sm_mm[k][cg][tx];
                }
                s[k] = ss * 0.125f;
                m[k] = mm;
            }
            float mx = fmaxf(fmaxf(s[0], s[1]), fmaxf(s[2], s[3]));
            float sum = 0.f, acc = 0.f;
            #pragma unroll
            for (int k = 0; k < 4; k++) {
                float e2 = expf(s[k] - mx);
                sum += e2;
                acc = fmaf(e2, m[k], acc);
            }
            float z = acc / sum + bb;
            conf += dw[f] / (1.f + expf(-z));
        }
        __syncthreads();
    }

    if (ty == 0) g_mask[b * HWc + p] = (conf > 0.5f) ? 1.0f : 0.0f;
}

// ---------------------------------------------------------------------------
// Kernel B: 3x3 max dilation (SAME)
// ---------------------------------------------------------------------------
__global__ void dilate_kernel() {
    int p = blockIdx.x * blockDim.x + threadIdx.x;
    int b = blockIdx.y;
    if (p >= HWc) return;
    int i = p / Wc, j = p % Wc;
    float m = 0.f;
    #pragma unroll
    for (int di = -1; di <= 1; di++) {
        int ii = i + di;
        if (ii < 0 || ii >= Hc) continue;
        #pragma unroll
        for (int dj = -1; dj <= 1; dj++) {
            int jj = j + dj;
            if (jj < 0 || jj >= Wc) continue;
            m = fmaxf(m, g_mask[b * HWc + ii * Wc + jj]);
        }
    }
    g_dmask[b * HWc + p] = m;
}

// ---------------------------------------------------------------------------
// Kernel C: warp + 5-way attention fusion, single pass, channel-split
// ---------------------------------------------------------------------------
struct Taps {
    int idx[4];
    float w[4];
};

__device__ __forceinline__ Taps make_taps(int b, int n, float gx, float gy, bool use_mask) {
    const float* th = g_theta + (b * Nc + n) * 6;
    float g0 = fmaf(th[0], gx, fmaf(th[1], gy, th[2]));
    float g1 = fmaf(th[3], gx, fmaf(th[4], gy, th[5]));
    float px = (g0 + 1.f) * 0.5f * (float)(Wc - 1);
    float py = (g1 + 1.f) * 0.5f * (float)(Hc - 1);
    float x0f = floorf(px), y0f = floorf(py);
    float wx = px - x0f, wy = py - y0f;
    int xi = (int)x0f, yi = (int)y0f;

    float bw[4] = { (1.f - wx) * (1.f - wy), wx * (1.f - wy),
                    (1.f - wx) * wy,         wx * wy };
    const int dx[4] = {0, 1, 0, 1};
    const int dy[4] = {0, 0, 1, 1};

    Taps t;
    #pragma unroll
    for (int tt = 0; tt < 4; tt++) {
        int xx = xi + dx[tt], yy = yi + dy[tt];
        bool valid = (xx >= 0) & (xx <= Wc - 1) & (yy >= 0) & (yy <= Hc - 1);
        int xc = min(max(xx, 0), Wc - 1);
        int yc = min(max(yy, 0), Hc - 1);
        int idx = yc * Wc + xc;
        float mv = use_mask ? g_dmask[b * HWc + idx] : 1.f;
        t.idx[tt] = idx;
        t.w[tt] = valid ? bw[tt] * mv : 0.f;
    }
    return t;
}

__device__ __forceinline__ float sample4(const float* __restrict__ img, const Taps& t) {
    return fmaf(t.w[0], __ldg(img + t.idx[0]),
           fmaf(t.w[1], __ldg(img + t.idx[1]),
           fmaf(t.w[2], __ldg(img + t.idx[2]),
                t.w[3] * __ldg(img + t.idx[3]))));
}

__global__ __launch_bounds__(PX * CG)
void fuse_kernel(const float* __restrict__ x0, float* __restrict__ out) {
    __shared__ float sm_s[Nc][CG][PX];

    int tx = threadIdx.x;
    int ty = threadIdx.y;
    int p  = blockIdx.x * PX + tx;
    int b  = blockIdx.y;
    int c0 = ty * CPT;

    int i = p / Wc, j = p % Wc;
    float gx = -1.f + 2.f * (float)j / (float)(Wc - 1);
    float gy = -1.f + 2.f * (float)i / (float)(Hc - 1);

    const float* xb = x0 + (size_t)b * Nc * Cc * HWc + (size_t)c0 * HWc;

    float v[Nc][CPT];

    // frame 0 (ego): no mask
    {
        Taps t0 = make_taps(b, 0, gx, gy, false);
        float ss = 0.f;
        #pragma unroll
        for (int cc = 0; cc < CPT; cc++) {
            float val = sample4(xb + (size_t)cc * HWc, t0);
            v[0][cc] = val;
            ss = fmaf(val, val, ss);
        }
        sm_s[0][ty][tx] = ss;
    }

    // frames 1..4: masked
    #pragma unroll
    for (int k = 1; k < Nc; k++) {
        Taps tk = make_taps(b, k, gx, gy, true);
        const float* imgb = xb + (size_t)k * Cc * HWc;
        float ss = 0.f;
        #pragma unroll
        for (int cc = 0; cc < CPT; cc++) {
            float val = sample4(imgb + (size_t)cc * HWc, tk);
            v[k][cc] = val;
            ss = fmaf(v[0][cc], val, ss);
        }
        sm_s[k][ty][tx] = ss;
    }
    __syncthreads();

    // per-thread (redundant) softmax from smem partials
    float s[Nc];
    #pragma unroll
    for (int k = 0; k < Nc; k++) {
        float ss = 0.f;
        #pragma unroll
        for (int cg = 0; cg < CG; cg++) ss += sm_s[k][cg][tx];
        s[k] = ss * 0.125f;
    }
    float mx = s[0];
    #pragma unroll
    for (int k = 1; k < Nc; k++) mx = fmaxf(mx, s[k]);
    float a[Nc], sum = 0.f;
    #pragma unroll
    for (int k = 0; k < Nc; k++) { a[k] = expf(s[k] - mx); sum += a[k]; }
    float inv = 1.f / sum;

    // fuse from registers and store
    #pragma unroll
    for (int cc = 0; cc < CPT; cc++) {
        float o = 0.f;
        #pragma unroll
        for (int k = 0; k < Nc; k++) o = fmaf(a[k], v[k][cc], o);
        out[((size_t)b * Cc + c0 + cc) * HWc + p] = o * inv;
    }
}

// ---------------------------------------------------------------------------
// Launch
// ---------------------------------------------------------------------------
extern "C" void kernel_launch(void* const* d_in, const int* in_sizes, int n_in,
                              void* d_out, int out_size) {
    const float* x0    = (const float*)d_in[0];
    const float* x1    = (const float*)d_in[1];
    const float* pt    = (const float*)d_in[2];
    const float* mlp_w = (const float*)d_in[3];
    const float* mlp_b = (const float*)d_in[4];
    float* out = (float*)d_out;

    theta_kernel<<<1, 32>>>(pt);

    dim3 blk(PX, CG);
    dim3 grid(HWc / PX, Bc);
    score_kernel<<<grid, blk>>>(x0, x1, mlp_w, mlp_b);

    dim3 gridB((HWc + 255) / 256, Bc);
    dilate_kernel<<<gridB, 256>>>();

    fuse_kernel<<<grid, blk>>>(x0, out);
}

// round 3
// speedup vs baseline: 2.2234x; 1.1253x over previous
#include <cuda_runtime.h>
#include <math.h>

#define Bc 4
#define Nc 5
#define Cc 64
#define Hc 96
#define Wc 288
#define HWc (Hc * Wc)

// DECAY_WEIGHTS = softmax([1.0, 0.5])
#define W0c 0.6224593312018546f
#define W1c 0.3775406687981454f

// score kernel tiling
#define SPX 32
#define SCG 16
#define SCPT 4

// fuse kernel tiling
#define FPX 32
#define FCG 32
#define FCPT 2

__device__ float g_theta[Bc * Nc * 6];
__device__ float g_mask[Bc * HWc];
__device__ float g_dmask[Bc * HWc];

// ---------------------------------------------------------------------------
// Kernel T: build 2x3 affine thetas from pairwise_t_matrix[b, 0, n]
// ---------------------------------------------------------------------------
__global__ void theta_kernel(const float* __restrict__ pt) {
    int t = threadIdx.x;
    if (t >= Bc * Nc) return;
    int b = t / Nc, n = t % Nc;
    const float* P = pt + ((size_t)(b * Nc + 0) * Nc + n) * 16;  // 4x4 row-major
    float* th = g_theta + t * 6;
    th[0] = P[0];
    th[1] = P[1] * ((float)Hc / (float)Wc);
    th[2] = P[3] / (4.0f * 0.4f * (float)Wc) * 2.0f;
    th[3] = P[4] * ((float)Wc / (float)Hc);
    th[4] = P[5];
    th[5] = P[7] / (4.0f * 0.4f * (float)Hc) * 2.0f;
}

// ---------------------------------------------------------------------------
// Kernel A: per-pixel confidence -> binary mask. Single barrier; both frames'
// partials staged in smem so all global loads overlap.
// ---------------------------------------------------------------------------
__global__ __launch_bounds__(SPX * SCG)
void score_kernel(const float* __restrict__ x0, const float* __restrict__ x1,
                  const float* __restrict__ mlp_w, const float* __restrict__ mlp_b) {
    __shared__ float sm_ss[2][4][SCG][SPX];
    __shared__ float sm_mm[2][4][SCG][SPX];

    int tx = threadIdx.x;
    int ty = threadIdx.y;
    int p  = blockIdx.x * SPX + tx;
    int b  = blockIdx.y;
    int c0 = ty * SCPT;

    float w[SCPT];
    #pragma unroll
    for (int cc = 0; cc < SCPT; cc++) w[cc] = __ldg(mlp_w + c0 + cc);

    #pragma unroll
    for (int f = 0; f < 2; f++) {
        const float* xf = (f == 0) ? x0 : x1;
        const float* base = xf + (size_t)b * Nc * Cc * HWc + (size_t)c0 * HWc + p;

        float e[SCPT];
        #pragma unroll
        for (int cc = 0; cc < SCPT; cc++) e[cc] = base[(size_t)cc * HWc];

        #pragma unroll
        for (int k = 0; k < 4; k++) {
            const float* nb = base + (size_t)(k + 1) * Cc * HWc;
            float ss = 0.f, mm = 0.f;
            #pragma unroll
            for (int cc = 0; cc < SCPT; cc++) {
                float v = nb[(size_t)cc * HWc];
                ss = fmaf(e[cc], v, ss);
                mm = fmaf(w[cc], v, mm);
            }
            sm_ss[f][k][ty][tx] = ss;
            sm_mm[f][k][ty][tx] = mm;
        }
    }
    __syncthreads();

    if (ty == 0) {
        float bb = __ldg(mlp_b);
        float conf = 0.f;
        const float dw[2] = {W0c, W1c};
        #pragma unroll
        for (int f = 0; f < 2; f++) {
            float s[4], m[4];
            #pragma unroll
            for (int k = 0; k < 4; k++) {
                float ss = 0.f, mm = 0.f;
                #pragma unroll
                for (int cg = 0; cg < SCG; cg++) {
                    ss += sm_ss[f][k][cg][tx];
                    mm += sm_mm[f][k][cg][tx];
                }
                s[k] = ss * 0.125f;
                m[k] = mm;
            }
            float mx = fmaxf(fmaxf(s[0], s[1]), fmaxf(s[2], s[3]));
            float sum = 0.f, acc = 0.f;
            #pragma unroll
            for (int k = 0; k < 4; k++) {
                float e2 = expf(s[k] - mx);
                sum += e2;
                acc = fmaf(e2, m[k], acc);
            }
            float z = acc / sum + bb;
            conf += dw[f] / (1.f + expf(-z));
        }
        g_mask[b * HWc + p] = (conf > 0.5f) ? 1.0f : 0.0f;
    }
}

// ---------------------------------------------------------------------------
// Kernel B: 3x3 max dilation (SAME)
// ---------------------------------------------------------------------------
__global__ void dilate_kernel() {
    int p = blockIdx.x * blockDim.x + threadIdx.x;
    int b = blockIdx.y;
    if (p >= HWc) return;
    int i = p / Wc, j = p % Wc;
    float m = 0.f;
    #pragma unroll
    for (int di = -1; di <= 1; di++) {
        int ii = i + di;
        if (ii < 0 || ii >= Hc) continue;
        #pragma unroll
        for (int dj = -1; dj <= 1; dj++) {
            int jj = j + dj;
            if (jj < 0 || jj >= Wc) continue;
            m = fmaxf(m, g_mask[b * HWc + ii * Wc + jj]);
        }
    }
    g_dmask[b * HWc + p] = m;
}

// ---------------------------------------------------------------------------
// Kernel C: warp + 5-way attention fusion
//   - taps precomputed once per (frame, pixel) into smem (SoA)
//   - weights premultiplied with validity + dilated mask
//   - 1024 threads, 2 channels/thread -> high occupancy
// ---------------------------------------------------------------------------
__global__ __launch_bounds__(FPX * FCG, 2)
void fuse_kernel(const float* __restrict__ x0, float* __restrict__ out) {
    __shared__ float sm_s[Nc][FCG][FPX];    // score partials
    __shared__ float sm_red[Nc][FPX];       // reduced scores
    // taps SoA
    __shared__ int   sm_b0[Nc][FPX];
    __shared__ int   sm_b1[Nc][FPX];
    __shared__ float sm_w00[Nc][FPX];
    __shared__ float sm_w01[Nc][FPX];
    __shared__ float sm_w10[Nc][FPX];
    __shared__ float sm_w11[Nc][FPX];

    int tx = threadIdx.x;
    int ty = threadIdx.y;
    int p  = blockIdx.x * FPX + tx;
    int b  = blockIdx.y;
    int tid = ty * FPX + tx;

    // ---- tap precompute: one thread per (frame, pixel) ----
    if (tid < Nc * FPX) {
        int n  = tid / FPX;
        int lx = tid - n * FPX;
        int pp = blockIdx.x * FPX + lx;
        int i = pp / Wc, j = pp - i * Wc;
        float gx = -1.f + 2.f * (float)j / (float)(Wc - 1);
        float gy = -1.f + 2.f * (float)i / (float)(Hc - 1);

        const float* th = g_theta + (b * Nc + n) * 6;
        float g0 = fmaf(th[0], gx, fmaf(th[1], gy, th[2]));
        float g1 = fmaf(th[3], gx, fmaf(th[4], gy, th[5]));
        float pxf = (g0 + 1.f) * 0.5f * (float)(Wc - 1);
        float pyf = (g1 + 1.f) * 0.5f * (float)(Hc - 1);
        float x0f = floorf(pxf), y0f = floorf(pyf);
        float wx = pxf - x0f, wy = pyf - y0f;
        int xi = (int)x0f, yi = (int)y0f;

        int r0 = min(max(yi, 0), Hc - 1) * Wc;
        int r1 = min(max(yi + 1, 0), Hc - 1) * Wc;
        float wy0 = (yi >= 0 && yi <= Hc - 1) ? (1.f - wy) : 0.f;
        float wy1 = (yi + 1 >= 0 && yi + 1 <= Hc - 1) ? wy : 0.f;

        int bx = min(max(xi, 0), Wc - 2);
        int sh = xi - bx;
        float ax0, ax1;
        if (sh == 0)        { ax0 = 1.f - wx; ax1 = wx;       }
        else if (sh == -1)  { ax0 = wx;       ax1 = 0.f;      }
        else if (sh == 1)   { ax0 = 0.f;      ax1 = 1.f - wx; }
        else                { ax0 = 0.f;      ax1 = 0.f;      }

        float m00 = 1.f, m01 = 1.f, m10 = 1.f, m11 = 1.f;
        if (n > 0) {
            const float* dm = g_dmask + b * HWc;
            m00 = dm[r0 + bx]; m01 = dm[r0 + bx + 1];
            m10 = dm[r1 + bx]; m11 = dm[r1 + bx + 1];
        }

        sm_b0[n][lx]  = r0 + bx;
        sm_b1[n][lx]  = r1 + bx;
        sm_w00[n][lx] = ax0 * wy0 * m00;
        sm_w01[n][lx] = ax1 * wy0 * m01;
        sm_w10[n][lx] = ax0 * wy1 * m10;
        sm_w11[n][lx] = ax1 * wy1 * m11;
    }
    __syncthreads();

    // ---- gather + score partials ----
    const float* xb = x0 + (size_t)b * Nc * Cc * HWc + (size_t)(ty * FCPT) * HWc;

    float v[Nc][FCPT];
    #pragma unroll
    for (int k = 0; k < Nc; k++) {
        int   b0  = sm_b0[k][tx];
        int   b1  = sm_b1[k][tx];
        float w00 = sm_w00[k][tx];
        float w01 = sm_w01[k][tx];
        float w10 = sm_w10[k][tx];
        float w11 = sm_w11[k][tx];
        const float* imgb = xb + (size_t)k * Cc * HWc;
        float ss = 0.f;
        #pragma unroll
        for (int cc = 0; cc < FCPT; cc++) {
            const float* im = imgb + (size_t)cc * HWc;
            float val = fmaf(w00, __ldg(im + b0),
                        fmaf(w01, __ldg(im + b0 + 1),
                        fmaf(w10, __ldg(im + b1),
                             w11 * __ldg(im + b1 + 1))));
            v[k][cc] = val;
            ss = fmaf(v[0][cc], val, ss);   // k==0: val*val
        }
        sm_s[k][ty][tx] = ss;
    }
    __syncthreads();

    // ---- parallel reduction: warp k reduces frame k ----
    if (ty < Nc) {
        float ssum = 0.f;
        #pragma unroll
        for (int cg = 0; cg < FCG; cg++) ssum += sm_s[ty][cg][tx];
        sm_red[ty][tx] = ssum * 0.125f;
    }
    __syncthreads();

    // ---- per-thread softmax (redundant, cheap) + fuse + store ----
    float s[Nc];
    #pragma unroll
    for (int k = 0; k < Nc; k++) s[k] = sm_red[k][tx];
    float mx = s[0];
    #pragma unroll
    for (int k = 1; k < Nc; k++) mx = fmaxf(mx, s[k]);
    float a[Nc], sum = 0.f;
    #pragma unroll
    for (int k = 0; k < Nc; k++) { a[k] = __expf(s[k] - mx); sum += a[k]; }
    float inv = 1.f / sum;

    int c0 = ty * FCPT;
    #pragma unroll
    for (int cc = 0; cc < FCPT; cc++) {
        float o = 0.f;
        #pragma unroll
        for (int k = 0; k < Nc; k++) o = fmaf(a[k], v[k][cc], o);
        out[((size_t)b * Cc + c0 + cc) * HWc + p] = o * inv;
    }
}

// ---------------------------------------------------------------------------
// Launch
// ---------------------------------------------------------------------------
extern "C" void kernel_launch(void* const* d_in, const int* in_sizes, int n_in,
                              void* d_out, int out_size) {
    const float* x0    = (const float*)d_in[0];
    const float* x1    = (const float*)d_in[1];
    const float* pt    = (const float*)d_in[2];
    const float* mlp_w = (const float*)d_in[3];
    const float* mlp_b = (const float*)d_in[4];
    float* out = (float*)d_out;

    theta_kernel<<<1, 32>>>(pt);

    dim3 blkS(SPX, SCG);
    dim3 gridS(HWc / SPX, Bc);
    score_kernel<<<gridS, blkS>>>(x0, x1, mlp_w, mlp_b);

    dim3 gridB((HWc + 255) / 256, Bc);
    dilate_kernel<<<gridB, 256>>>();

    dim3 blkF(FPX, FCG);
    dim3 gridF(HWc / FPX, Bc);
    fuse_kernel<<<gridF, blkF>>>(x0, out);
}